// round 15
// baseline (speedup 1.0000x reference)
#include <cuda_runtime.h>
#include <cuda_fp16.h>
#include <cstdint>
#include <math.h>

// Problem constants
#define D_NODE 256
#define D_PAIR 128
#define NHEAD  8
#define NSEQ   128
#define NRES   256
#define NROWS  (NSEQ * NRES)          // 32768
#define EPROJ  1024                    // 768 qkv + 256 gate

#define LOG2E 1.4426950408889634f

// Scratch (all fp16 single-precision operands)
__device__ __half g_M[(size_t)NROWS * D_NODE];       // LN(M)
__device__ __half g_W[(size_t)EPROJ * D_NODE];       // [Wqkv;Wgate]
__device__ __half g_O[(size_t)D_NODE * D_NODE];      // W_o
__device__ __half g_X[(size_t)NROWS * 768];          // q(scaled)|k|v
__device__ __half g_gate[(size_t)NROWS * 256];       // gate logits
__device__ __half g_pb[(size_t)NHEAD * NRES * NRES]; // pair bias*log2e [h][q][k]
__device__ __half g_A[(size_t)NROWS * D_NODE];       // gated attn out

__device__ __forceinline__ uint32_t smem_u32(const void* p) {
    uint32_t a;
    asm("{ .reg .u64 t; cvta.to.shared.u64 t, %1; cvt.u32.u64 %0, t; }"
        : "=r"(a) : "l"(p));
    return a;
}

#define LDM_X4(r0, r1, r2, r3, addr)                                           \
    asm volatile("ldmatrix.sync.aligned.m8n8.x4.shared.b16 {%0,%1,%2,%3}, [%4];" \
                 : "=r"(r0), "=r"(r1), "=r"(r2), "=r"(r3) : "r"(addr))
#define LDM_A(v, addr) LDM_X4((v)[0], (v)[1], (v)[2], (v)[3], addr)

#define LDM_T(v, addr)                                                         \
    asm volatile("ldmatrix.sync.aligned.m8n8.x4.trans.shared.b16 {%0,%1,%2,%3}, [%4];" \
                 : "=r"((v)[0]), "=r"((v)[1]), "=r"((v)[2]), "=r"((v)[3]) : "r"(addr))

#define MMA_F16(d, a, b0, b1)                                                  \
    asm volatile("mma.sync.aligned.m16n8k16.row.col.f32.f16.f16.f32 "          \
                 "{%0,%1,%2,%3}, {%4,%5,%6,%7}, {%8,%9}, {%0,%1,%2,%3};"       \
                 : "+f"((d)[0]), "+f"((d)[1]), "+f"((d)[2]), "+f"((d)[3])      \
                 : "r"((a)[0]), "r"((a)[1]), "r"((a)[2]), "r"((a)[3]),         \
                   "r"(b0), "r"(b1))

#define CP16(s, g)                                                             \
    asm volatile("cp.async.cg.shared.global [%0], [%1], 16;" :: "r"(s), "l"(g))
#define CP_COMMIT() asm volatile("cp.async.commit_group;" ::: "memory")

__device__ __forceinline__ uint32_t pk2(float lo, float hi) {
    __half2 h = __floats2half2_rn(lo, hi);
    return *reinterpret_cast<uint32_t*>(&h);
}
__device__ __forceinline__ float2 h2f2(uint32_t u) {
    __half2 h = *reinterpret_cast<__half2*>(&u);
    return __half22float2(h);
}
__device__ __forceinline__ float ex2(float x) {
    float r;
    asm("ex2.approx.f32 %0, %1;" : "=f"(r) : "f"(x));
    return r;
}
__device__ __forceinline__ uint32_t ex2_h2(uint32_t x) {
    uint32_t r;
    asm("ex2.approx.f16x2 %0, %1;" : "=r"(r) : "r"(x));
    return r;
}

__device__ __forceinline__ float warp_sum(float v) {
#pragma unroll
    for (int o = 16; o > 0; o >>= 1) v += __shfl_xor_sync(0xffffffffu, v, o);
    return v;
}

// ---------------------------------------------------------------------------
// Kernel 1 (fused preprocessing): ln_m | wconv | wconv_o | pair  -> fp16
// ---------------------------------------------------------------------------
#define PREP_LN  4096
#define PREP_WC  (PREP_LN + 1024)   // 5120
#define PREP_WO  (PREP_WC + 256)    // 5376
#define PREP_TOT (PREP_WO + 8192)   // 13568

__global__ __launch_bounds__(256) void prep_kernel(
    const float* __restrict__ M_raw, const float* __restrict__ mlsc,
    const float* __restrict__ mlbi,
    const float* __restrict__ Wq, const float* __restrict__ Wg,
    const float* __restrict__ Wo,
    const float* __restrict__ Z, const float* __restrict__ zsc,
    const float* __restrict__ zbi, const float* __restrict__ Wb)
{
    __shared__ float swb[1024];
    __shared__ float ssc[128], sbi[128];
    __shared__ float spb[64];

    int b = blockIdx.x;
    int tid = threadIdx.x;

    if (b < PREP_LN) {
        int w = tid >> 5, l = tid & 31;
        int row = b * 8 + w;
        const float4* xr = (const float4*)(M_raw + (size_t)row * 256);
        float4 a = xr[l], bb = xr[l + 32];
        float s1 = (a.x + a.y) + (a.z + a.w) + (bb.x + bb.y) + (bb.z + bb.w);
        float s2 = a.x * a.x + a.y * a.y + a.z * a.z + a.w * a.w
                 + bb.x * bb.x + bb.y * bb.y + bb.z * bb.z + bb.w * bb.w;
        s1 = warp_sum(s1);
        s2 = warp_sum(s2);
        float mu  = s1 * (1.0f / 256.0f);
        float var = s2 * (1.0f / 256.0f) - mu * mu;
        float inv = rsqrtf(var + 1e-5f);

        float4 sa = ((const float4*)mlsc)[l], sb4 = ((const float4*)mlsc)[l + 32];
        float4 ba = ((const float4*)mlbi)[l], bb4 = ((const float4*)mlbi)[l + 32];

        __half* mh = g_M + (size_t)row * 256;
        int c = l * 4;
        *(__half2*)(mh + c) = __floats2half2_rn(
            (a.x - mu) * inv * sa.x + ba.x, (a.y - mu) * inv * sa.y + ba.y);
        *(__half2*)(mh + c + 2) = __floats2half2_rn(
            (a.z - mu) * inv * sa.z + ba.z, (a.w - mu) * inv * sa.w + ba.w);
        c += 128;
        *(__half2*)(mh + c) = __floats2half2_rn(
            (bb.x - mu) * inv * sb4.x + bb4.x, (bb.y - mu) * inv * sb4.y + bb4.y);
        *(__half2*)(mh + c + 2) = __floats2half2_rn(
            (bb.z - mu) * inv * sb4.z + bb4.z, (bb.w - mu) * inv * sb4.w + bb4.w);
    } else if (b < PREP_WC) {
        int i = (b - PREP_LN) * 256 + tid;
        float v = (i < 768 * 256) ? Wq[i] : Wg[i - 768 * 256];
        g_W[i] = __float2half_rn(v);
    } else if (b < PREP_WO) {
        int i = (b - PREP_WC) * 256 + tid;
        g_O[i] = __float2half_rn(Wo[i]);
    } else {
        int pb = b - PREP_WO;
        if (tid < 128) { ssc[tid] = zsc[tid]; sbi[tid] = zbi[tid]; }
        ((float4*)swb)[tid] = ((const float4*)Wb)[tid];
        __syncthreads();

        int w = tid >> 5, l = tid & 31;
        int row = pb * 8 + w;                // = q*256 + k
        float4 z = ((const float4*)(Z + (size_t)row * 128))[l];
        float s1 = (z.x + z.y) + (z.z + z.w);
        float s2 = z.x * z.x + z.y * z.y + z.z * z.z + z.w * z.w;
        s1 = warp_sum(s1);
        s2 = warp_sum(s2);
        float mu  = s1 * (1.0f / 128.0f);
        float var = s2 * (1.0f / 128.0f) - mu * mu;
        float inv = rsqrtf(var + 1e-5f);
        int c = l * 4;
        float zn0 = (z.x - mu) * inv * ssc[c]     + sbi[c];
        float zn1 = (z.y - mu) * inv * ssc[c + 1] + sbi[c + 1];
        float zn2 = (z.z - mu) * inv * ssc[c + 2] + sbi[c + 2];
        float zn3 = (z.w - mu) * inv * ssc[c + 3] + sbi[c + 3];

        float p[8];
#pragma unroll
        for (int hh = 0; hh < 8; hh++) {
            float4 wb4 = ((const float4*)swb)[hh * 32 + l];
            p[hh] = zn0 * wb4.x + zn1 * wb4.y + zn2 * wb4.z + zn3 * wb4.w;
        }
#pragma unroll
        for (int hh = 0; hh < 8; hh++) p[hh] += __shfl_xor_sync(0xffffffffu, p[hh], 16);
        float q0 = (l & 16) ? p[4] : p[0];
        float q1 = (l & 16) ? p[5] : p[1];
        float q2 = (l & 16) ? p[6] : p[2];
        float q3 = (l & 16) ? p[7] : p[3];
        q0 += __shfl_xor_sync(0xffffffffu, q0, 8);
        q1 += __shfl_xor_sync(0xffffffffu, q1, 8);
        q2 += __shfl_xor_sync(0xffffffffu, q2, 8);
        q3 += __shfl_xor_sync(0xffffffffu, q3, 8);
        float r0 = (l & 8) ? q2 : q0;
        float r1 = (l & 8) ? q3 : q1;
        r0 += __shfl_xor_sync(0xffffffffu, r0, 4);
        r1 += __shfl_xor_sync(0xffffffffu, r1, 4);
        float s0 = (l & 4) ? r1 : r0;
        s0 += __shfl_xor_sync(0xffffffffu, s0, 2);
        s0 += __shfl_xor_sync(0xffffffffu, s0, 1);
        if ((l & 3) == 0) spb[w * 8 + (l >> 2)] = s0 * LOG2E;
        __syncthreads();
        if (tid < 64) {
            int hh = tid >> 3, j = tid & 7;
            int row0 = pb * 8;
            int qq = row0 >> 8, k0 = row0 & 255;
            g_pb[(size_t)hh * 65536 + qq * 256 + k0 + j] = __float2half_rn(spb[j * 8 + hh]);
        }
    }
}

// ---------------------------------------------------------------------------
// Kernel 3: projection GEMM (mma.sync fp16, 3-stage cp.async pipeline).
// ---------------------------------------------------------------------------
#define PSTG_A 0
#define PSTG_B 10240
#define PSTAGE 20480
#define PSMEM  (3 * PSTAGE)

__global__ __launch_bounds__(256) void gemm_proj_mma()
{
    extern __shared__ __align__(16) unsigned char smb[];
    uint32_t sbase = smem_u32(smb);
    int tid = threadIdx.x;
    int lane = tid & 31, wid = tid >> 5;
    int wm = wid >> 2, wn = wid & 3;
    int bm = blockIdx.y * 128, bn = blockIdx.x * 128;

    float acc[4][4][4] = {};

    int lrow = tid >> 1, lhalf = tid & 1;
    size_t gA = (size_t)(bm + lrow) * 256 + lhalf * 16;
    size_t gB = (size_t)(bn + lrow) * 256 + lhalf * 16;
    uint32_t sOff = lrow * 80 + lhalf * 32;

    uint32_t aRow = (lane & 15);
    uint32_t aChunk = (lane >> 4) << 3;
    uint32_t bRow = (lane & 7) + ((lane >> 4) << 3);
    uint32_t bChunk = ((lane >> 3) & 1) << 3;

    // prologue: stage tiles 0 and 1
#pragma unroll
    for (int c = 0; c < 2; c++) {
        uint32_t b = sbase + c * PSTAGE;
        const __half* p;
        p = g_M + gA + c * 32;
        CP16(b + PSTG_A + sOff, p); CP16(b + PSTG_A + sOff + 16, p + 8);
        p = g_W + gB + c * 32;
        CP16(b + PSTG_B + sOff, p); CP16(b + PSTG_B + sOff + 16, p + 8);
        CP_COMMIT();
    }

#pragma unroll 1
    for (int t = 0; t < 8; t++) {
        if (t + 2 < 8) {
            int c = t + 2;
            uint32_t b = sbase + (c % 3) * PSTAGE;
            const __half* p;
            p = g_M + gA + c * 32;
            CP16(b + PSTG_A + sOff, p); CP16(b + PSTG_A + sOff + 16, p + 8);
            p = g_W + gB + c * 32;
            CP16(b + PSTG_B + sOff, p); CP16(b + PSTG_B + sOff + 16, p + 8);
            CP_COMMIT();
            asm volatile("cp.async.wait_group 2;" ::: "memory");
        } else if (t + 1 < 8) {
            asm volatile("cp.async.wait_group 1;" ::: "memory");
        } else {
            asm volatile("cp.async.wait_group 0;" ::: "memory");
        }
        __syncthreads();

        uint32_t sb = sbase + (t % 3) * PSTAGE;
#pragma unroll
        for (int ks = 0; ks < 2; ks++) {
            uint32_t ah[4][4], bh[2][4];
#pragma unroll
            for (int mi = 0; mi < 4; mi++) {
                uint32_t ad = sb + PSTG_A + (wm * 64 + mi * 16 + aRow) * 80
                            + (ks * 16 + aChunk) * 2;
                LDM_A(ah[mi], ad);
            }
#pragma unroll
            for (int ng = 0; ng < 2; ng++) {
                uint32_t bd = sb + PSTG_B + (wn * 32 + ng * 16 + bRow) * 80
                            + (ks * 16 + bChunk) * 2;
                LDM_A(bh[ng], bd);
            }
#pragma unroll
            for (int mi = 0; mi < 4; mi++) {
#pragma unroll
                for (int nj = 0; nj < 4; nj++) {
                    int ng = nj >> 1, sub = (nj & 1) * 2;
                    MMA_F16(acc[mi][nj], ah[mi], bh[ng][sub], bh[ng][sub + 1]);
                }
            }
        }
        __syncthreads();
    }

    int r0 = bm + wm * 64 + (lane >> 2);
    int c0 = bn + wn * 32 + (lane & 3) * 2;
    if (bn < 768) {
        float sc = (bn < 256) ? (0.17677669529663688f * LOG2E) : 1.0f;
#pragma unroll
        for (int mi = 0; mi < 4; mi++) {
#pragma unroll
            for (int nj = 0; nj < 4; nj++) {
                int c = c0 + nj * 8;
#pragma unroll
                for (int p = 0; p < 2; p++) {
                    int r = r0 + mi * 16 + p * 8;
                    *(__half2*)(g_X + (size_t)r * 768 + c) =
                        __floats2half2_rn(acc[mi][nj][2 * p] * sc,
                                          acc[mi][nj][2 * p + 1] * sc);
                }
            }
        }
    } else {
#pragma unroll
        for (int mi = 0; mi < 4; mi++) {
#pragma unroll
            for (int nj = 0; nj < 4; nj++) {
                int c = c0 + nj * 8 - 768;
#pragma unroll
                for (int p = 0; p < 2; p++) {
                    int r = r0 + mi * 16 + p * 8;
                    *(__half2*)(g_gate + (size_t)r * 256 + c) =
                        __floats2half2_rn(acc[mi][nj][2 * p], acc[mi][nj][2 * p + 1]);
                }
            }
        }
    }
}

// ---------------------------------------------------------------------------
// Kernel 4: flash attention, fp16 single-term, f16x2 softmax exp.
// Single pb buffer (99KB smem -> 2 CTAs/SM).
// ---------------------------------------------------------------------------
#define OQ  0
#define OK  20480
#define OV  40960
#define OPB 61440
#define OMB (OPB + 36864)             // 98304
#define ATTN_SMEM (OMB + 1024)        // 99328

__global__ __launch_bounds__(256) void attn_mma(
    const float* __restrict__ mask, const float* __restrict__ gbias)
{
    extern __shared__ __align__(16) unsigned char smb[];
    uint32_t sb = smem_u32(smb);
    int tid = threadIdx.x;
    int lane = tid & 31, w = tid >> 5;
    int h = blockIdx.x, s = blockIdx.y;

    const __half* XB = g_X + (size_t)s * 256 * 768;

#pragma unroll 1
    for (int i = tid; i < 1024; i += 256) {
        int r = i >> 2, seg = i & 3;
        uint32_t d = r * 80 + seg * 16;
        size_t off = (size_t)r * 768 + h * 32 + seg * 8;
        CP16(sb + OQ + d, XB + off);
        CP16(sb + OK + d, XB + off + 256);
        CP16(sb + OV + d, XB + off + 512);
    }
    {
        const __half* pbB = g_pb + (size_t)h * 65536;
#pragma unroll 1
        for (int i = tid; i < 2048; i += 256) {
            int q = i >> 3, seg = i & 7;
            CP16(sb + OPB + q * 144 + seg * 16, pbB + (size_t)q * 256 + seg * 8);
        }
    }
    CP_COMMIT();
    ((float*)(smb + OMB))[tid] = (1e9f * LOG2E) * (mask[s * 256 + tid] - 1.0f);
    asm volatile("cp.async.wait_group 0;" ::: "memory");
    __syncthreads();

    uint32_t aRow = lane & 15, aChunk = (lane >> 4) << 3;
    uint32_t bRow = (lane & 7) + ((lane >> 4) << 3);
    uint32_t bChunk = ((lane >> 3) & 1) << 3;
    uint32_t vkRow = (lane & 7) + (((lane >> 3) & 1) << 3);
    uint32_t vcCol = (lane >> 4) << 3;

    uint32_t ah[2][2][4];
#pragma unroll
    for (int mi = 0; mi < 2; mi++)
#pragma unroll
        for (int ks = 0; ks < 2; ks++) {
            uint32_t ad = sb + OQ + (w * 32 + mi * 16 + aRow) * 80
                        + (ks * 16 + aChunk) * 2;
            LDM_A(ah[mi][ks], ad);
        }

    float o[2][4][4] = {};
    float mrow[4] = {-1e30f, -1e30f, -1e30f, -1e30f};
    float srow[4] = {};

#pragma unroll 1
    for (int kb = 0; kb < 4; kb++) {
        float sfr[2][8][4] = {};
        // S = Q K^T (single fp16 term)
#pragma unroll
        for (int ks = 0; ks < 2; ks++)
#pragma unroll
            for (int ng = 0; ng < 4; ng++) {
                uint32_t kh[4];
                uint32_t bd = sb + OK + (kb * 64 + ng * 16 + bRow) * 80
                            + (ks * 16 + bChunk) * 2;
                LDM_A(kh, bd);
#pragma unroll
                for (int mi = 0; mi < 2; mi++) {
                    MMA_F16(sfr[mi][ng * 2], ah[mi][ks], kh[0], kh[1]);
                    MMA_F16(sfr[mi][ng * 2 + 1], ah[mi][ks], kh[2], kh[3]);
                }
            }

        // add mask bias + pair bias (consume pb buffer)
        const float* mbp = (const float*)(smb + OMB) + kb * 64;
#pragma unroll
        for (int mi = 0; mi < 2; mi++) {
            int q0 = w * 32 + mi * 16 + (lane >> 2);
#pragma unroll
            for (int nj = 0; nj < 8; nj++) {
                int cB = nj * 8 + (lane & 3) * 2;
                float2 mv = *(const float2*)(mbp + cB);
                uint32_t u0, u1;
                asm("ld.shared.b32 %0, [%1];" : "=r"(u0) : "r"(sb + OPB + q0 * 144 + cB * 2));
                asm("ld.shared.b32 %0, [%1];" : "=r"(u1) : "r"(sb + OPB + (q0 + 8) * 144 + cB * 2));
                float2 p0 = h2f2(u0), p1 = h2f2(u1);
                sfr[mi][nj][0] += mv.x + p0.x;
                sfr[mi][nj][1] += mv.y + p0.y;
                sfr[mi][nj][2] += mv.x + p1.x;
                sfr[mi][nj][3] += mv.y + p1.y;
            }
        }

        // pb consumed by all warps; prefetch next kb tile into the same buffer
        if (kb < 3) {
            __syncthreads();
            const __half* pbB = g_pb + (size_t)h * 65536 + (kb + 1) * 64;
#pragma unroll 1
            for (int i = tid; i < 2048; i += 256) {
                int q = i >> 3, seg = i & 7;
                CP16(sb + OPB + q * 144 + seg * 16, pbB + (size_t)q * 256 + seg * 8);
            }
            CP_COMMIT();
        }

        // online softmax (exp via f16x2 MUFU; result doubles as PV A-operand)
#pragma unroll
        for (int mi = 0; mi < 2; mi++)
#pragma unroll
            for (int p = 0; p < 2; p++) {
                int id = mi * 2 + p;
                float mx = mrow[id];
#pragma unroll
                for (int nj = 0; nj < 8; nj++)
                    mx = fmaxf(mx, fmaxf(sfr[mi][nj][2 * p], sfr[mi][nj][2 * p + 1]));
                mx = fmaxf(mx, __shfl_xor_sync(0xffffffffu, mx, 1));
                mx = fmaxf(mx, __shfl_xor_sync(0xffffffffu, mx, 2));
                float es = ex2(mrow[id] - mx);
                mrow[id] = mx;
                float ls = 0.f;
#pragma unroll
                for (int nj = 0; nj < 8; nj++) {
                    uint32_t pe = ex2_h2(pk2(sfr[mi][nj][2 * p] - mx,
                                             sfr[mi][nj][2 * p + 1] - mx));
                    float2 pf = h2f2(pe);
                    ls += pf.x + pf.y;
                    sfr[mi][nj][2 * p] = __uint_as_float(pe);
                }
                ls += __shfl_xor_sync(0xffffffffu, ls, 1);
                ls += __shfl_xor_sync(0xffffffffu, ls, 2);
                srow[id] = srow[id] * es + ls;
#pragma unroll
                for (int nc = 0; nc < 4; nc++) {
                    o[mi][nc][2 * p] *= es;
                    o[mi][nc][2 * p + 1] *= es;
                }
            }

        // O += P V
#pragma unroll
        for (int t = 0; t < 4; t++) {
            uint32_t pa[2][4];
#pragma unroll
            for (int mi = 0; mi < 2; mi++) {
                pa[mi][0] = __float_as_uint(sfr[mi][2 * t][0]);
                pa[mi][1] = __float_as_uint(sfr[mi][2 * t][2]);
                pa[mi][2] = __float_as_uint(sfr[mi][2 * t + 1][0]);
                pa[mi][3] = __float_as_uint(sfr[mi][2 * t + 1][2]);
            }
#pragma unroll
            for (int ng = 0; ng < 2; ng++) {
                uint32_t vh[4];
                uint32_t vd = sb + OV + (kb * 64 + t * 16 + vkRow) * 80
                            + (ng * 16 + vcCol) * 2;
                LDM_T(vh, vd);
#pragma unroll
                for (int mi = 0; mi < 2; mi++) {
                    MMA_F16(o[mi][ng * 2], pa[mi], vh[0], vh[1]);
                    MMA_F16(o[mi][ng * 2 + 1], pa[mi], vh[2], vh[3]);
                }
            }
        }

        if (kb < 3) {
            asm volatile("cp.async.wait_group 0;" ::: "memory");
            __syncthreads();
        }
    }
    __syncthreads();

    // epilogue part 1: stage normalized O in smem
    float* stg = (float*)smb;
#pragma unroll
    for (int mi = 0; mi < 2; mi++)
#pragma unroll
        for (int p = 0; p < 2; p++) {
            float inv = 1.0f / srow[mi * 2 + p];
            int rr = w * 32 + mi * 16 + (lane >> 2) + p * 8;
#pragma unroll
            for (int nc = 0; nc < 4; nc++) {
                int cc = nc * 8 + (lane & 3) * 2;
                *(float2*)(stg + rr * 36 + cc) =
                    make_float2(o[mi][nc][2 * p] * inv, o[mi][nc][2 * p + 1] * inv);
            }
        }
    __syncthreads();

    // epilogue part 2: coalesced gated write-out
    {
        int seg = tid & 7;
        int rbase = tid >> 3;
        int gc = h * 32 + seg * 4;
        float4 gb4 = *(const float4*)(gbias + gc);
#pragma unroll
        for (int pass = 0; pass < 8; pass++) {
            int rr = pass * 32 + rbase;
            size_t gr = (size_t)(s * 256 + rr) * 256 + gc;
            float4 ov = *(float4*)(stg + rr * 36 + seg * 4);
            uint2 gu = *(const uint2*)(g_gate + gr);
            float2 gl0 = h2f2(gu.x), gl1 = h2f2(gu.y);
            float a0 = ov.x / (1.0f + __expf(-(gl0.x + gb4.x)));
            float a1 = ov.y / (1.0f + __expf(-(gl0.y + gb4.y)));
            float a2 = ov.z / (1.0f + __expf(-(gl1.x + gb4.z)));
            float a3 = ov.w / (1.0f + __expf(-(gl1.y + gb4.w)));
            uint2 hv;
            hv.x = pk2(a0, a1);
            hv.y = pk2(a2, a3);
            *(uint2*)(g_A + gr) = hv;
        }
    }
}

// ---------------------------------------------------------------------------
// Kernel 5: out = A @ W_o^T + M_raw + out_bias.  BM=128 BN=64, 3-stage.
// ---------------------------------------------------------------------------
#define GO_A 0
#define GO_B 10240
#define GO_STAGE 15360
#define GO_SMEM  (3 * GO_STAGE)   // 46080

__global__ __launch_bounds__(256) void gemm_out_mma(
    const float* __restrict__ Mraw, const float* __restrict__ obias,
    float* __restrict__ out)
{
    extern __shared__ __align__(16) unsigned char smb[];
    uint32_t sbase = smem_u32(smb);
    int tid = threadIdx.x;
    int lane = tid & 31, wid = tid >> 5;
    int wm = wid >> 1, wn = wid & 1;           // 4 x 2 warp grid
    int bm = blockIdx.y * 128, bn = blockIdx.x * 64;

    float acc[2][4][4] = {};

    int lrow = tid >> 1, lhalf = tid & 1;
    size_t gA = (size_t)(bm + lrow) * 256 + lhalf * 16;
    uint32_t sOffA = lrow * 80 + lhalf * 32;
    size_t gB = (size_t)(bn + (lrow & 63)) * 256 + lhalf * 16;
    uint32_t sOffB = (lrow & 63) * 80 + lhalf * 32;
    bool doB = (tid < 128);

    uint32_t aRow = (lane & 15);
    uint32_t aChunk = (lane >> 4) << 3;
    uint32_t bRow = (lane & 7) + ((lane >> 4) << 3);
    uint32_t bChunk = ((lane >> 3) & 1) << 3;

    // prologue: stage tiles 0 and 1
#pragma unroll
    for (int c = 0; c < 2; c++) {
        uint32_t b = sbase + c * GO_STAGE;
        const __half* p;
        p = g_A + gA + c * 32;
        CP16(b + GO_A + sOffA, p); CP16(b + GO_A + sOffA + 16, p + 8);
        if (doB) {
            p = g_O + gB + c * 32;
            CP16(b + GO_B + sOffB, p); CP16(b + GO_B + sOffB + 16, p + 8);
        }
        CP_COMMIT();
    }

#pragma unroll 1
    for (int t = 0; t < 8; t++) {
        if (t + 2 < 8) {
            int c = t + 2;
            uint32_t b = sbase + (c % 3) * GO_STAGE;
            const __half* p;
            p = g_A + gA + c * 32;
            CP16(b + GO_A + sOffA, p); CP16(b + GO_A + sOffA + 16, p + 8);
            if (doB) {
                p = g_O + gB + c * 32;
                CP16(b + GO_B + sOffB, p); CP16(b + GO_B + sOffB + 16, p + 8);
            }
            CP_COMMIT();
            asm volatile("cp.async.wait_group 2;" ::: "memory");
        } else if (t + 1 < 8) {
            asm volatile("cp.async.wait_group 1;" ::: "memory");
        } else {
            asm volatile("cp.async.wait_group 0;" ::: "memory");
        }
        __syncthreads();

        uint32_t sb = sbase + (t % 3) * GO_STAGE;
#pragma unroll
        for (int ks = 0; ks < 2; ks++) {
            uint32_t ah[2][4], bh[2][4];
#pragma unroll
            for (int mi = 0; mi < 2; mi++) {
                uint32_t ad = sb + GO_A + (wm * 32 + mi * 16 + aRow) * 80
                            + (ks * 16 + aChunk) * 2;
                LDM_A(ah[mi], ad);
            }
#pragma unroll
            for (int ng = 0; ng < 2; ng++) {
                uint32_t bd = sb + GO_B + (wn * 32 + ng * 16 + bRow) * 80
                            + (ks * 16 + bChunk) * 2;
                LDM_A(bh[ng], bd);
            }
#pragma unroll
            for (int mi = 0; mi < 2; mi++) {
#pragma unroll
                for (int nj = 0; nj < 4; nj++) {
                    int ng = nj >> 1, sub = (nj & 1) * 2;
                    MMA_F16(acc[mi][nj], ah[mi], bh[ng][sub], bh[ng][sub + 1]);
                }
            }
        }
        __syncthreads();
    }

    int r0 = bm + wm * 32 + (lane >> 2);
    int c0 = bn + wn * 32 + (lane & 3) * 2;
#pragma unroll
    for (int mi = 0; mi < 2; mi++) {
#pragma unroll
        for (int nj = 0; nj < 4; nj++) {
            int r = r0 + mi * 16, c = c0 + nj * 8;
            float ob0 = obias[c], ob1 = obias[c + 1];
            float2 m0 = *(const float2*)(Mraw + (size_t)r * 256 + c);
            *(float2*)(out + (size_t)r * 256 + c) =
                make_float2(acc[mi][nj][0] + m0.x + ob0, acc[mi][nj][1] + m0.y + ob1);
            float2 m1 = *(const float2*)(Mraw + (size_t)(r + 8) * 256 + c);
            *(float2*)(out + (size_t)(r + 8) * 256 + c) =
                make_float2(acc[mi][nj][2] + m1.x + ob0, acc[mi][nj][3] + m1.y + ob1);
        }
    }
}

// ---------------------------------------------------------------------------
extern "C" void kernel_launch(void* const* d_in, const int* in_sizes, int n_in,
                              void* d_out, int out_size)
{
    const float* M_raw      = (const float*)d_in[0];
    const float* Z          = (const float*)d_in[1];
    const float* M_mask     = (const float*)d_in[2];
    const float* ln_m_scale = (const float*)d_in[3];
    const float* ln_m_bias  = (const float*)d_in[4];
    const float* ln_z_scale = (const float*)d_in[5];
    const float* ln_z_bias  = (const float*)d_in[6];
    const float* W_b        = (const float*)d_in[7];
    const float* W_qkv      = (const float*)d_in[8];
    const float* W_gate     = (const float*)d_in[9];
    const float* gbias      = (const float*)d_in[10];
    const float* W_o        = (const float*)d_in[11];
    const float* out_bias   = (const float*)d_in[12];
    float* out = (float*)d_out;

    cudaFuncSetAttribute(attn_mma, cudaFuncAttributeMaxDynamicSharedMemorySize,
                         ATTN_SMEM);
    cudaFuncSetAttribute(gemm_proj_mma, cudaFuncAttributeMaxDynamicSharedMemorySize,
                         PSMEM);
    cudaFuncSetAttribute(gemm_out_mma, cudaFuncAttributeMaxDynamicSharedMemorySize,
                         GO_SMEM);

    prep_kernel<<<PREP_TOT, 256>>>(M_raw, ln_m_scale, ln_m_bias,
                                   W_qkv, W_gate, W_o,
                                   Z, ln_z_scale, ln_z_bias, W_b);
    gemm_proj_mma<<<dim3(EPROJ / 128, NROWS / 128), 256, PSMEM>>>();
    attn_mma<<<dim3(NHEAD, NSEQ), 256, ATTN_SMEM>>>(M_mask, gbias);
    gemm_out_mma<<<dim3(256 / 64, NROWS / 128), 256, GO_SMEM>>>(M_raw, out_bias, out);
}

// round 17
// speedup vs baseline: 1.0425x; 1.0425x over previous
#include <cuda_runtime.h>
#include <cuda_fp16.h>
#include <cstdint>
#include <math.h>

// Problem constants
#define D_NODE 256
#define D_PAIR 128
#define NHEAD  8
#define NSEQ   128
#define NRES   256
#define NROWS  (NSEQ * NRES)          // 32768
#define EPROJ  1024                    // 768 qkv + 256 gate

#define LOG2E 1.4426950408889634f

// Scratch (all fp16 single-precision operands)
__device__ __half g_M[(size_t)NROWS * D_NODE];       // LN(M)
__device__ __half g_W[(size_t)EPROJ * D_NODE];       // [Wqkv;Wgate]
__device__ __half g_O[(size_t)D_NODE * D_NODE];      // W_o
__device__ __half g_X[(size_t)NROWS * 768];          // q(scaled)|k|v
__device__ __half g_gate[(size_t)NROWS * 256];       // gate logits
__device__ __half g_pb[(size_t)NHEAD * NRES * NRES]; // pair bias*log2e [h][q][k]
__device__ __half g_A[(size_t)NROWS * D_NODE];       // gated attn out

__device__ __forceinline__ uint32_t smem_u32(const void* p) {
    uint32_t a;
    asm("{ .reg .u64 t; cvta.to.shared.u64 t, %1; cvt.u32.u64 %0, t; }"
        : "=r"(a) : "l"(p));
    return a;
}

#define LDM_X4(r0, r1, r2, r3, addr)                                           \
    asm volatile("ldmatrix.sync.aligned.m8n8.x4.shared.b16 {%0,%1,%2,%3}, [%4];" \
                 : "=r"(r0), "=r"(r1), "=r"(r2), "=r"(r3) : "r"(addr))
#define LDM_A(v, addr) LDM_X4((v)[0], (v)[1], (v)[2], (v)[3], addr)

#define LDM_T(v, addr)                                                         \
    asm volatile("ldmatrix.sync.aligned.m8n8.x4.trans.shared.b16 {%0,%1,%2,%3}, [%4];" \
                 : "=r"((v)[0]), "=r"((v)[1]), "=r"((v)[2]), "=r"((v)[3]) : "r"(addr))

#define MMA_F16(d, a, b0, b1)                                                  \
    asm volatile("mma.sync.aligned.m16n8k16.row.col.f32.f16.f16.f32 "          \
                 "{%0,%1,%2,%3}, {%4,%5,%6,%7}, {%8,%9}, {%0,%1,%2,%3};"       \
                 : "+f"((d)[0]), "+f"((d)[1]), "+f"((d)[2]), "+f"((d)[3])      \
                 : "r"((a)[0]), "r"((a)[1]), "r"((a)[2]), "r"((a)[3]),         \
                   "r"(b0), "r"(b1))

#define CP16(s, g)                                                             \
    asm volatile("cp.async.cg.shared.global [%0], [%1], 16;" :: "r"(s), "l"(g))
#define CP_COMMIT() asm volatile("cp.async.commit_group;" ::: "memory")

__device__ __forceinline__ uint32_t pk2(float lo, float hi) {
    __half2 h = __floats2half2_rn(lo, hi);
    return *reinterpret_cast<uint32_t*>(&h);
}
__device__ __forceinline__ float2 h2f2(uint32_t u) {
    __half2 h = *reinterpret_cast<__half2*>(&u);
    return __half22float2(h);
}
__device__ __forceinline__ float ex2(float x) {
    float r;
    asm("ex2.approx.f32 %0, %1;" : "=f"(r) : "f"(x));
    return r;
}
__device__ __forceinline__ uint32_t ex2_h2(uint32_t x) {
    uint32_t r;
    asm("ex2.approx.f16x2 %0, %1;" : "=r"(r) : "r"(x));
    return r;
}

// ---------------------------------------------------------------------------
// Kernel 1 (fused preprocessing): ln_m | wconv | wconv_o | pair  -> fp16
// Sub-warp row groups: LN 16 lanes/row (2 rows/warp), pair 8 lanes/row
// (4 rows/warp) -> shuffle issue per row cut 2.5-5x.
// ---------------------------------------------------------------------------
#define PREP_LN  2048                 // 16 rows per CTA
#define PREP_WC  (PREP_LN + 1024)     // 3072
#define PREP_WO  (PREP_WC + 256)      // 3328
#define PREP_TOT (PREP_WO + 2048)     // 5376 (pair: 32 rows per CTA)

__global__ __launch_bounds__(256) void prep_kernel(
    const float* __restrict__ M_raw, const float* __restrict__ mlsc,
    const float* __restrict__ mlbi,
    const float* __restrict__ Wq, const float* __restrict__ Wg,
    const float* __restrict__ Wo,
    const float* __restrict__ Z, const float* __restrict__ zsc,
    const float* __restrict__ zbi, const float* __restrict__ Wb)
{
    __shared__ float swb[1024];
    __shared__ float ssc[128], sbi[128];
    __shared__ float spb[256];        // [32 rows][8 heads]

    int b = blockIdx.x;
    int tid = threadIdx.x;

    if (b < PREP_LN) {
        // ---- LN(M): 16 lanes per row, 2 rows per warp, 16 rows per CTA ----
        int w = tid >> 5, l = tid & 31;
        int grp = l >> 4, j = l & 15;
        int row = b * 16 + w * 2 + grp;
        const float4* xr = (const float4*)(M_raw + (size_t)row * 256);
        float4 v0 = xr[j], v1 = xr[j + 16], v2 = xr[j + 32], v3 = xr[j + 48];
        float s1 = (v0.x + v0.y) + (v0.z + v0.w) + (v1.x + v1.y) + (v1.z + v1.w)
                 + (v2.x + v2.y) + (v2.z + v2.w) + (v3.x + v3.y) + (v3.z + v3.w);
        float s2 = v0.x * v0.x + v0.y * v0.y + v0.z * v0.z + v0.w * v0.w
                 + v1.x * v1.x + v1.y * v1.y + v1.z * v1.z + v1.w * v1.w
                 + v2.x * v2.x + v2.y * v2.y + v2.z * v2.z + v2.w * v2.w
                 + v3.x * v3.x + v3.y * v3.y + v3.z * v3.z + v3.w * v3.w;
#pragma unroll
        for (int o = 8; o > 0; o >>= 1) {
            s1 += __shfl_xor_sync(0xffffffffu, s1, o);
            s2 += __shfl_xor_sync(0xffffffffu, s2, o);
        }
        float mu  = s1 * (1.0f / 256.0f);
        float var = s2 * (1.0f / 256.0f) - mu * mu;
        float inv = rsqrtf(var + 1e-5f);

        __half* mh = g_M + (size_t)row * 256;
        float4 vv[4] = {v0, v1, v2, v3};
#pragma unroll
        for (int m = 0; m < 4; m++) {
            int fi = j + 16 * m;
            float4 sc4 = ((const float4*)mlsc)[fi];
            float4 bi4 = ((const float4*)mlbi)[fi];
            float y0 = (vv[m].x - mu) * inv * sc4.x + bi4.x;
            float y1 = (vv[m].y - mu) * inv * sc4.y + bi4.y;
            float y2 = (vv[m].z - mu) * inv * sc4.z + bi4.z;
            float y3 = (vv[m].w - mu) * inv * sc4.w + bi4.w;
            uint2 hv;
            hv.x = pk2(y0, y1);
            hv.y = pk2(y2, y3);
            *(uint2*)(mh + fi * 4) = hv;
        }
    } else if (b < PREP_WC) {
        int i = (b - PREP_LN) * 256 + tid;
        float v = (i < 768 * 256) ? Wq[i] : Wg[i - 768 * 256];
        g_W[i] = __float2half_rn(v);
    } else if (b < PREP_WO) {
        int i = (b - PREP_WC) * 256 + tid;
        g_O[i] = __float2half_rn(Wo[i]);
    } else {
        // ---- LN(Z)+pair: 8 lanes per row, 4 rows per warp, 32 rows/CTA ----
        int pb = b - PREP_WO;
        if (tid < 128) { ssc[tid] = zsc[tid]; sbi[tid] = zbi[tid]; }
        ((float4*)swb)[tid] = ((const float4*)Wb)[tid];
        __syncthreads();

        int w = tid >> 5, l = tid & 31;
        int sub = l >> 3, j = l & 7;
        int rowInCta = w * 4 + sub;
        int row = pb * 32 + rowInCta;        // = q*256 + k
        const float4* zr = (const float4*)(Z + (size_t)row * 128);
        float4 z0 = zr[j], z1 = zr[j + 8], z2 = zr[j + 16], z3 = zr[j + 24];
        float s1 = (z0.x + z0.y) + (z0.z + z0.w) + (z1.x + z1.y) + (z1.z + z1.w)
                 + (z2.x + z2.y) + (z2.z + z2.w) + (z3.x + z3.y) + (z3.z + z3.w);
        float s2 = z0.x * z0.x + z0.y * z0.y + z0.z * z0.z + z0.w * z0.w
                 + z1.x * z1.x + z1.y * z1.y + z1.z * z1.z + z1.w * z1.w
                 + z2.x * z2.x + z2.y * z2.y + z2.z * z2.z + z2.w * z2.w
                 + z3.x * z3.x + z3.y * z3.y + z3.z * z3.z + z3.w * z3.w;
#pragma unroll
        for (int o = 4; o > 0; o >>= 1) {
            s1 += __shfl_xor_sync(0xffffffffu, s1, o);
            s2 += __shfl_xor_sync(0xffffffffu, s2, o);
        }
        float mu  = s1 * (1.0f / 128.0f);
        float var = s2 * (1.0f / 128.0f) - mu * mu;
        float inv = rsqrtf(var + 1e-5f);

        float4 zz[4] = {z0, z1, z2, z3};
        float4 zn[4];
#pragma unroll
        for (int m = 0; m < 4; m++) {
            int fi = j + 8 * m;
            float4 sc4 = ((const float4*)ssc)[fi];
            float4 bi4 = ((const float4*)sbi)[fi];
            zn[m].x = (zz[m].x - mu) * inv * sc4.x + bi4.x;
            zn[m].y = (zz[m].y - mu) * inv * sc4.y + bi4.y;
            zn[m].z = (zz[m].z - mu) * inv * sc4.z + bi4.z;
            zn[m].w = (zz[m].w - mu) * inv * sc4.w + bi4.w;
        }

        float p[8];
#pragma unroll
        for (int hh = 0; hh < 8; hh++) {
            float acc = 0.f;
#pragma unroll
            for (int m = 0; m < 4; m++) {
                float4 wb4 = ((const float4*)swb)[hh * 32 + j + 8 * m];
                acc += zn[m].x * wb4.x + zn[m].y * wb4.y
                     + zn[m].z * wb4.z + zn[m].w * wb4.w;
            }
            p[hh] = acc;
        }
        // fold reduction over 8-lane group; lane j ends with head j's sum
#pragma unroll
        for (int hh = 0; hh < 8; hh++) p[hh] += __shfl_xor_sync(0xffffffffu, p[hh], 4);
        float q0 = (j & 4) ? p[4] : p[0];
        float q1 = (j & 4) ? p[5] : p[1];
        float q2 = (j & 4) ? p[6] : p[2];
        float q3 = (j & 4) ? p[7] : p[3];
        q0 += __shfl_xor_sync(0xffffffffu, q0, 2);
        q1 += __shfl_xor_sync(0xffffffffu, q1, 2);
        q2 += __shfl_xor_sync(0xffffffffu, q2, 2);
        q3 += __shfl_xor_sync(0xffffffffu, q3, 2);
        float r0 = (j & 2) ? q2 : q0;
        float r1 = (j & 2) ? q3 : q1;
        r0 += __shfl_xor_sync(0xffffffffu, r0, 1);
        r1 += __shfl_xor_sync(0xffffffffu, r1, 1);
        float s0 = (j & 1) ? r1 : r0;
        spb[rowInCta * 8 + j] = s0 * LOG2E;
        __syncthreads();

        // coalesced write-out: thread tid -> head tid>>5, k-offset tid&31
        int hh = tid >> 5, kk = tid & 31;
        int row0 = pb * 32;
        int qq = row0 >> 8, k0 = row0 & 255;
        g_pb[(size_t)hh * 65536 + qq * 256 + k0 + kk] =
            __float2half_rn(spb[kk * 8 + hh]);
    }
}

// ---------------------------------------------------------------------------
// Kernel 3: projection GEMM (mma.sync fp16 single-term, cp.async 2-stage).
// ---------------------------------------------------------------------------
#define PSTG_A 0
#define PSTG_B 10240
#define PSTAGE 20480
#define PSMEM  (2 * PSTAGE)

__global__ __launch_bounds__(256) void gemm_proj_mma()
{
    extern __shared__ __align__(16) unsigned char smb[];
    uint32_t sbase = smem_u32(smb);
    int tid = threadIdx.x;
    int lane = tid & 31, wid = tid >> 5;
    int wm = wid >> 2, wn = wid & 3;
    int bm = blockIdx.y * 128, bn = blockIdx.x * 128;

    float acc[4][4][4] = {};

    int lrow = tid >> 1, lhalf = tid & 1;
    size_t gA = (size_t)(bm + lrow) * 256 + lhalf * 16;
    size_t gB = (size_t)(bn + lrow) * 256 + lhalf * 16;
    uint32_t sOff = lrow * 80 + lhalf * 32;

    uint32_t aRow = (lane & 15);
    uint32_t aChunk = (lane >> 4) << 3;
    uint32_t bRow = (lane & 7) + ((lane >> 4) << 3);
    uint32_t bChunk = ((lane >> 3) & 1) << 3;

    {
        uint32_t b = sbase;
        CP16(b + PSTG_A + sOff, g_M + gA); CP16(b + PSTG_A + sOff + 16, g_M + gA + 8);
        CP16(b + PSTG_B + sOff, g_W + gB); CP16(b + PSTG_B + sOff + 16, g_W + gB + 8);
        CP_COMMIT();
    }

#pragma unroll 1
    for (int t = 0; t < 8; t++) {
        if (t < 7) {
            int c = t + 1;
            uint32_t b = sbase + (c & 1) * PSTAGE;
            const __half* p;
            p = g_M + gA + c * 32;
            CP16(b + PSTG_A + sOff, p); CP16(b + PSTG_A + sOff + 16, p + 8);
            p = g_W + gB + c * 32;
            CP16(b + PSTG_B + sOff, p); CP16(b + PSTG_B + sOff + 16, p + 8);
            CP_COMMIT();
            asm volatile("cp.async.wait_group 1;" ::: "memory");
        } else {
            asm volatile("cp.async.wait_group 0;" ::: "memory");
        }
        __syncthreads();

        uint32_t sb = sbase + (t & 1) * PSTAGE;
#pragma unroll
        for (int ks = 0; ks < 2; ks++) {
            uint32_t ah[4][4], bh[2][4];
#pragma unroll
            for (int mi = 0; mi < 4; mi++) {
                uint32_t ad = sb + PSTG_A + (wm * 64 + mi * 16 + aRow) * 80
                            + (ks * 16 + aChunk) * 2;
                LDM_A(ah[mi], ad);
            }
#pragma unroll
            for (int ng = 0; ng < 2; ng++) {
                uint32_t bd = sb + PSTG_B + (wn * 32 + ng * 16 + bRow) * 80
                            + (ks * 16 + bChunk) * 2;
                LDM_A(bh[ng], bd);
            }
#pragma unroll
            for (int mi = 0; mi < 4; mi++) {
#pragma unroll
                for (int nj = 0; nj < 4; nj++) {
                    int ng = nj >> 1, sub = (nj & 1) * 2;
                    MMA_F16(acc[mi][nj], ah[mi], bh[ng][sub], bh[ng][sub + 1]);
                }
            }
        }
        __syncthreads();
    }

    int r0 = bm + wm * 64 + (lane >> 2);
    int c0 = bn + wn * 32 + (lane & 3) * 2;
    if (bn < 768) {
        float sc = (bn < 256) ? (0.17677669529663688f * LOG2E) : 1.0f;
#pragma unroll
        for (int mi = 0; mi < 4; mi++) {
#pragma unroll
            for (int nj = 0; nj < 4; nj++) {
                int c = c0 + nj * 8;
#pragma unroll
                for (int p = 0; p < 2; p++) {
                    int r = r0 + mi * 16 + p * 8;
                    *(__half2*)(g_X + (size_t)r * 768 + c) =
                        __floats2half2_rn(acc[mi][nj][2 * p] * sc,
                                          acc[mi][nj][2 * p + 1] * sc);
                }
            }
        }
    } else {
#pragma unroll
        for (int mi = 0; mi < 4; mi++) {
#pragma unroll
            for (int nj = 0; nj < 4; nj++) {
                int c = c0 + nj * 8 - 768;
#pragma unroll
                for (int p = 0; p < 2; p++) {
                    int r = r0 + mi * 16 + p * 8;
                    *(__half2*)(g_gate + (size_t)r * 256 + c) =
                        __floats2half2_rn(acc[mi][nj][2 * p], acc[mi][nj][2 * p + 1]);
                }
            }
        }
    }
}

// ---------------------------------------------------------------------------
// Kernel 4: flash attention, fp16 single-term, f16x2 softmax exp.
// Single pb buffer (99KB smem -> 2 CTAs/SM).
// ---------------------------------------------------------------------------
#define OQ  0
#define OK  20480
#define OV  40960
#define OPB 61440
#define OMB (OPB + 36864)             // 98304
#define ATTN_SMEM (OMB + 1024)        // 99328

__global__ __launch_bounds__(256) void attn_mma(
    const float* __restrict__ mask, const float* __restrict__ gbias)
{
    extern __shared__ __align__(16) unsigned char smb[];
    uint32_t sb = smem_u32(smb);
    int tid = threadIdx.x;
    int lane = tid & 31, w = tid >> 5;
    int h = blockIdx.x, s = blockIdx.y;

    const __half* XB = g_X + (size_t)s * 256 * 768;

#pragma unroll 1
    for (int i = tid; i < 1024; i += 256) {
        int r = i >> 2, seg = i & 3;
        uint32_t d = r * 80 + seg * 16;
        size_t off = (size_t)r * 768 + h * 32 + seg * 8;
        CP16(sb + OQ + d, XB + off);
        CP16(sb + OK + d, XB + off + 256);
        CP16(sb + OV + d, XB + off + 512);
    }
    {
        const __half* pbB = g_pb + (size_t)h * 65536;
#pragma unroll 1
        for (int i = tid; i < 2048; i += 256) {
            int q = i >> 3, seg = i & 7;
            CP16(sb + OPB + q * 144 + seg * 16, pbB + (size_t)q * 256 + seg * 8);
        }
    }
    CP_COMMIT();
    ((float*)(smb + OMB))[tid] = (1e9f * LOG2E) * (mask[s * 256 + tid] - 1.0f);
    asm volatile("cp.async.wait_group 0;" ::: "memory");
    __syncthreads();

    uint32_t aRow = lane & 15, aChunk = (lane >> 4) << 3;
    uint32_t bRow = (lane & 7) + ((lane >> 4) << 3);
    uint32_t bChunk = ((lane >> 3) & 1) << 3;
    uint32_t vkRow = (lane & 7) + (((lane >> 3) & 1) << 3);
    uint32_t vcCol = (lane >> 4) << 3;

    uint32_t ah[2][2][4];
#pragma unroll
    for (int mi = 0; mi < 2; mi++)
#pragma unroll
        for (int ks = 0; ks < 2; ks++) {
            uint32_t ad = sb + OQ + (w * 32 + mi * 16 + aRow) * 80
                        + (ks * 16 + aChunk) * 2;
            LDM_A(ah[mi][ks], ad);
        }

    float o[2][4][4] = {};
    float mrow[4] = {-1e30f, -1e30f, -1e30f, -1e30f};
    float srow[4] = {};

#pragma unroll 1
    for (int kb = 0; kb < 4; kb++) {
        float sfr[2][8][4] = {};
        // S = Q K^T (single fp16 term)
#pragma unroll
        for (int ks = 0; ks < 2; ks++)
#pragma unroll
            for (int ng = 0; ng < 4; ng++) {
                uint32_t kh[4];
                uint32_t bd = sb + OK + (kb * 64 + ng * 16 + bRow) * 80
                            + (ks * 16 + bChunk) * 2;
                LDM_A(kh, bd);
#pragma unroll
                for (int mi = 0; mi < 2; mi++) {
                    MMA_F16(sfr[mi][ng * 2], ah[mi][ks], kh[0], kh[1]);
                    MMA_F16(sfr[mi][ng * 2 + 1], ah[mi][ks], kh[2], kh[3]);
                }
            }

        // add mask bias + pair bias (consume pb buffer)
        const float* mbp = (const float*)(smb + OMB) + kb * 64;
#pragma unroll
        for (int mi = 0; mi < 2; mi++) {
            int q0 = w * 32 + mi * 16 + (lane >> 2);
#pragma unroll
            for (int nj = 0; nj < 8; nj++) {
                int cB = nj * 8 + (lane & 3) * 2;
                float2 mv = *(const float2*)(mbp + cB);
                uint32_t u0, u1;
                asm("ld.shared.b32 %0, [%1];" : "=r"(u0) : "r"(sb + OPB + q0 * 144 + cB * 2));
                asm("ld.shared.b32 %0, [%1];" : "=r"(u1) : "r"(sb + OPB + (q0 + 8) * 144 + cB * 2));
                float2 p0 = h2f2(u0), p1 = h2f2(u1);
                sfr[mi][nj][0] += mv.x + p0.x;
                sfr[mi][nj][1] += mv.y + p0.y;
                sfr[mi][nj][2] += mv.x + p1.x;
                sfr[mi][nj][3] += mv.y + p1.y;
            }
        }

        // pb consumed by all warps; prefetch next kb tile into the same buffer
        if (kb < 3) {
            __syncthreads();
            const __half* pbB = g_pb + (size_t)h * 65536 + (kb + 1) * 64;
#pragma unroll 1
            for (int i = tid; i < 2048; i += 256) {
                int q = i >> 3, seg = i & 7;
                CP16(sb + OPB + q * 144 + seg * 16, pbB + (size_t)q * 256 + seg * 8);
            }
            CP_COMMIT();
        }

        // online softmax (exp via f16x2 MUFU; result doubles as PV A-operand)
#pragma unroll
        for (int mi = 0; mi < 2; mi++)
#pragma unroll
            for (int p = 0; p < 2; p++) {
                int id = mi * 2 + p;
                float mx = mrow[id];
#pragma unroll
                for (int nj = 0; nj < 8; nj++)
                    mx = fmaxf(mx, fmaxf(sfr[mi][nj][2 * p], sfr[mi][nj][2 * p + 1]));
                mx = fmaxf(mx, __shfl_xor_sync(0xffffffffu, mx, 1));
                mx = fmaxf(mx, __shfl_xor_sync(0xffffffffu, mx, 2));
                float es = ex2(mrow[id] - mx);
                mrow[id] = mx;
                float ls = 0.f;
#pragma unroll
                for (int nj = 0; nj < 8; nj++) {
                    uint32_t pe = ex2_h2(pk2(sfr[mi][nj][2 * p] - mx,
                                             sfr[mi][nj][2 * p + 1] - mx));
                    float2 pf = h2f2(pe);
                    ls += pf.x + pf.y;
                    sfr[mi][nj][2 * p] = __uint_as_float(pe);
                }
                ls += __shfl_xor_sync(0xffffffffu, ls, 1);
                ls += __shfl_xor_sync(0xffffffffu, ls, 2);
                srow[id] = srow[id] * es + ls;
#pragma unroll
                for (int nc = 0; nc < 4; nc++) {
                    o[mi][nc][2 * p] *= es;
                    o[mi][nc][2 * p + 1] *= es;
                }
            }

        // O += P V
#pragma unroll
        for (int t = 0; t < 4; t++) {
            uint32_t pa[2][4];
#pragma unroll
            for (int mi = 0; mi < 2; mi++) {
                pa[mi][0] = __float_as_uint(sfr[mi][2 * t][0]);
                pa[mi][1] = __float_as_uint(sfr[mi][2 * t][2]);
                pa[mi][2] = __float_as_uint(sfr[mi][2 * t + 1][0]);
                pa[mi][3] = __float_as_uint(sfr[mi][2 * t + 1][2]);
            }
#pragma unroll
            for (int ng = 0; ng < 2; ng++) {
                uint32_t vh[4];
                uint32_t vd = sb + OV + (kb * 64 + t * 16 + vkRow) * 80
                            + (ng * 16 + vcCol) * 2;
                LDM_T(vh, vd);
#pragma unroll
                for (int mi = 0; mi < 2; mi++) {
                    MMA_F16(o[mi][ng * 2], pa[mi], vh[0], vh[1]);
                    MMA_F16(o[mi][ng * 2 + 1], pa[mi], vh[2], vh[3]);
                }
            }
        }

        if (kb < 3) {
            asm volatile("cp.async.wait_group 0;" ::: "memory");
            __syncthreads();
        }
    }
    __syncthreads();

    // epilogue part 1: stage normalized O in smem
    float* stg = (float*)smb;
#pragma unroll
    for (int mi = 0; mi < 2; mi++)
#pragma unroll
        for (int p = 0; p < 2; p++) {
            float inv = 1.0f / srow[mi * 2 + p];
            int rr = w * 32 + mi * 16 + (lane >> 2) + p * 8;
#pragma unroll
            for (int nc = 0; nc < 4; nc++) {
                int cc = nc * 8 + (lane & 3) * 2;
                *(float2*)(stg + rr * 36 + cc) =
                    make_float2(o[mi][nc][2 * p] * inv, o[mi][nc][2 * p + 1] * inv);
            }
        }
    __syncthreads();

    // epilogue part 2: coalesced gated write-out
    {
        int seg = tid & 7;
        int rbase = tid >> 3;
        int gc = h * 32 + seg * 4;
        float4 gb4 = *(const float4*)(gbias + gc);
#pragma unroll
        for (int pass = 0; pass < 8; pass++) {
            int rr = pass * 32 + rbase;
            size_t gr = (size_t)(s * 256 + rr) * 256 + gc;
            float4 ov = *(float4*)(stg + rr * 36 + seg * 4);
            uint2 gu = *(const uint2*)(g_gate + gr);
            float2 gl0 = h2f2(gu.x), gl1 = h2f2(gu.y);
            float a0 = ov.x / (1.0f + __expf(-(gl0.x + gb4.x)));
            float a1 = ov.y / (1.0f + __expf(-(gl0.y + gb4.y)));
            float a2 = ov.z / (1.0f + __expf(-(gl1.x + gb4.z)));
            float a3 = ov.w / (1.0f + __expf(-(gl1.y + gb4.w)));
            uint2 hv;
            hv.x = pk2(a0, a1);
            hv.y = pk2(a2, a3);
            *(uint2*)(g_A + gr) = hv;
        }
    }
}

// ---------------------------------------------------------------------------
// Kernel 5: out = A @ W_o^T + M_raw + out_bias.  BM=128 BN=64, 2-stage.
// ---------------------------------------------------------------------------
#define GO_A 0
#define GO_B 10240
#define GO_STAGE 15360
#define GO_SMEM  (2 * GO_STAGE)   // 30720

__global__ __launch_bounds__(256) void gemm_out_mma(
    const float* __restrict__ Mraw, const float* __restrict__ obias,
    float* __restrict__ out)
{
    extern __shared__ __align__(16) unsigned char smb[];
    uint32_t sbase = smem_u32(smb);
    int tid = threadIdx.x;
    int lane = tid & 31, wid = tid >> 5;
    int wm = wid >> 1, wn = wid & 1;           // 4 x 2 warp grid
    int bm = blockIdx.y * 128, bn = blockIdx.x * 64;

    float acc[2][4][4] = {};

    int lrow = tid >> 1, lhalf = tid & 1;
    size_t gA = (size_t)(bm + lrow) * 256 + lhalf * 16;
    uint32_t sOffA = lrow * 80 + lhalf * 32;
    size_t gB = (size_t)(bn + (lrow & 63)) * 256 + lhalf * 16;
    uint32_t sOffB = (lrow & 63) * 80 + lhalf * 32;
    bool doB = (tid < 128);

    uint32_t aRow = (lane & 15);
    uint32_t aChunk = (lane >> 4) << 3;
    uint32_t bRow = (lane & 7) + ((lane >> 4) << 3);
    uint32_t bChunk = ((lane >> 3) & 1) << 3;

    {
        uint32_t b = sbase;
        CP16(b + GO_A + sOffA, g_A + gA); CP16(b + GO_A + sOffA + 16, g_A + gA + 8);
        if (doB) {
            CP16(b + GO_B + sOffB, g_O + gB); CP16(b + GO_B + sOffB + 16, g_O + gB + 8);
        }
        CP_COMMIT();
    }

#pragma unroll 1
    for (int t = 0; t < 8; t++) {
        if (t < 7) {
            int c = t + 1;
            uint32_t b = sbase + (c & 1) * GO_STAGE;
            const __half* p;
            p = g_A + gA + c * 32;
            CP16(b + GO_A + sOffA, p); CP16(b + GO_A + sOffA + 16, p + 8);
            if (doB) {
                p = g_O + gB + c * 32;
                CP16(b + GO_B + sOffB, p); CP16(b + GO_B + sOffB + 16, p + 8);
            }
            CP_COMMIT();
            asm volatile("cp.async.wait_group 1;" ::: "memory");
        } else {
            asm volatile("cp.async.wait_group 0;" ::: "memory");
        }
        __syncthreads();

        uint32_t sb = sbase + (t & 1) * GO_STAGE;
#pragma unroll
        for (int ks = 0; ks < 2; ks++) {
            uint32_t ah[2][4], bh[2][4];
#pragma unroll
            for (int mi = 0; mi < 2; mi++) {
                uint32_t ad = sb + GO_A + (wm * 32 + mi * 16 + aRow) * 80
                            + (ks * 16 + aChunk) * 2;
                LDM_A(ah[mi], ad);
            }
#pragma unroll
            for (int ng = 0; ng < 2; ng++) {
                uint32_t bd = sb + GO_B + (wn * 32 + ng * 16 + bRow) * 80
                            + (ks * 16 + bChunk) * 2;
                LDM_A(bh[ng], bd);
            }
#pragma unroll
            for (int mi = 0; mi < 2; mi++) {
#pragma unroll
                for (int nj = 0; nj < 4; nj++) {
                    int ng = nj >> 1, sub = (nj & 1) * 2;
                    MMA_F16(acc[mi][nj], ah[mi], bh[ng][sub], bh[ng][sub + 1]);
                }
            }
        }
        __syncthreads();
    }

    int r0 = bm + wm * 32 + (lane >> 2);
    int c0 = bn + wn * 32 + (lane & 3) * 2;
#pragma unroll
    for (int mi = 0; mi < 2; mi++) {
#pragma unroll
        for (int nj = 0; nj < 4; nj++) {
            int r = r0 + mi * 16, c = c0 + nj * 8;
            float ob0 = obias[c], ob1 = obias[c + 1];
            float2 m0 = *(const float2*)(Mraw + (size_t)r * 256 + c);
            *(float2*)(out + (size_t)r * 256 + c) =
                make_float2(acc[mi][nj][0] + m0.x + ob0, acc[mi][nj][1] + m0.y + ob1);
            float2 m1 = *(const float2*)(Mraw + (size_t)(r + 8) * 256 + c);
            *(float2*)(out + (size_t)(r + 8) * 256 + c) =
                make_float2(acc[mi][nj][2] + m1.x + ob0, acc[mi][nj][3] + m1.y + ob1);
        }
    }
}

// ---------------------------------------------------------------------------
extern "C" void kernel_launch(void* const* d_in, const int* in_sizes, int n_in,
                              void* d_out, int out_size)
{
    const float* M_raw      = (const float*)d_in[0];
    const float* Z          = (const float*)d_in[1];
    const float* M_mask     = (const float*)d_in[2];
    const float* ln_m_scale = (const float*)d_in[3];
    const float* ln_m_bias  = (const float*)d_in[4];
    const float* ln_z_scale = (const float*)d_in[5];
    const float* ln_z_bias  = (const float*)d_in[6];
    const float* W_b        = (const float*)d_in[7];
    const float* W_qkv      = (const float*)d_in[8];
    const float* W_gate     = (const float*)d_in[9];
    const float* gbias      = (const float*)d_in[10];
    const float* W_o        = (const float*)d_in[11];
    const float* out_bias   = (const float*)d_in[12];
    float* out = (float*)d_out;

    cudaFuncSetAttribute(attn_mma, cudaFuncAttributeMaxDynamicSharedMemorySize,
                         ATTN_SMEM);

    prep_kernel<<<PREP_TOT, 256>>>(M_raw, ln_m_scale, ln_m_bias,
                                   W_qkv, W_gate, W_o,
                                   Z, ln_z_scale, ln_z_bias, W_b);
    gemm_proj_mma<<<dim3(EPROJ / 128, NROWS / 128), 256, PSMEM>>>();
    attn_mma<<<dim3(NHEAD, NSEQ), 256, ATTN_SMEM>>>(M_mask, gbias);
    gemm_out_mma<<<dim3(256 / 64, NROWS / 128), 256, GO_SMEM>>>(M_raw, out_bias, out);
}